// round 1
// baseline (speedup 1.0000x reference)
#include <cuda_runtime.h>

// Problem constants (fixed shapes from reference)
static constexpr int B = 8;
static constexpr int C = 128;
static constexpr int H = 56, W = 56;
static constexpr int N = H * W;                 // 3136
static constexpr size_t NN = (size_t)N * N;     // 9,834,496
static constexpr size_t XE = (size_t)B * C * N; // 3,211,264 elements per tensor

// Scratch: masked energy -> attention, per batch. ~315 MB static device array.
__device__ float g_E[(size_t)B * NN];

// ---------------------------------------------------------------------------
// K1: E[b] = V^T V with diagonal zeroed (multiplicative mask), V = x[b] as [C][N].
// Symmetric: only tiles tj >= ti computed; mirror written via smem transpose.
// grid (49, 49, B), block (16,16). 64x64 output tile, K-chunk 16 (C=128 total).
// ---------------------------------------------------------------------------
__global__ void k1_gram(const float* __restrict__ x) {
    const int ti = blockIdx.x, tj = blockIdx.y, b = blockIdx.z;
    if (tj < ti) return;

    __shared__ float As[16][64];
    __shared__ float Bs[16][64];
    __shared__ float T[64][65];   // transpose staging for mirrored tile

    const float* V = x + (size_t)b * C * N;
    const int tx = threadIdx.x, ty = threadIdx.y;
    const int tid = ty * 16 + tx;
    const int i0 = ti * 64, j0 = tj * 64;

    float acc[4][4] = {};

    for (int c0 = 0; c0 < C; c0 += 16) {
        // 16x64 = 1024 elements per tile, 256 threads -> 4 each, coalesced on N
        #pragma unroll
        for (int r = 0; r < 4; r++) {
            int e = tid + r * 256;
            int cc = e >> 6, col = e & 63;
            As[cc][col] = V[(size_t)(c0 + cc) * N + i0 + col];
            Bs[cc][col] = V[(size_t)(c0 + cc) * N + j0 + col];
        }
        __syncthreads();

        #pragma unroll
        for (int cc = 0; cc < 16; cc++) {
            float a[4], bb[4];
            #pragma unroll
            for (int r = 0; r < 4; r++) a[r] = As[cc][ty * 4 + r];
            #pragma unroll
            for (int s = 0; s < 4; s++) bb[s] = Bs[cc][tx * 4 + s];
            #pragma unroll
            for (int r = 0; r < 4; r++)
                #pragma unroll
                for (int s = 0; s < 4; s++)
                    acc[r][s] += a[r] * bb[s];
        }
        __syncthreads();
    }

    float* E = g_E + (size_t)b * NN;

    // Direct tile write with diagonal mask (energy * (1 - eye) -> 0 on diag)
    #pragma unroll
    for (int r = 0; r < 4; r++) {
        int i = i0 + ty * 4 + r;
        #pragma unroll
        for (int s = 0; s < 4; s++) {
            int j = j0 + tx * 4 + s;
            E[(size_t)i * N + j] = (i == j) ? 0.0f : acc[r][s];
        }
    }

    if (ti != tj) {
        // mirrored tile E[j][i] — stage through smem for coalesced stores
        #pragma unroll
        for (int r = 0; r < 4; r++)
            #pragma unroll
            for (int s = 0; s < 4; s++)
                T[tx * 4 + s][ty * 4 + r] = acc[r][s];
        __syncthreads();
        for (int e = tid; e < 64 * 64; e += 256) {
            int jj = e >> 6, ii = e & 63;
            E[(size_t)(j0 + jj) * N + i0 + ii] = T[jj][ii];
        }
    }
}

// ---------------------------------------------------------------------------
// K2: row softmax over axis j. One block per (row i, batch b); row cached in smem.
// grid (N, B), block 256.
// ---------------------------------------------------------------------------
__global__ void k2_softmax() {
    const int row = blockIdx.x, b = blockIdx.y;
    float* E = g_E + (size_t)b * NN + (size_t)row * N;

    __shared__ float sv[N];        // 12544 B
    __shared__ float red[256];
    const int tid = threadIdx.x;

    float m = -1e30f;
    for (int j = tid; j < N; j += 256) {
        float v = E[j];
        sv[j] = v;
        m = fmaxf(m, v);
    }
    red[tid] = m;
    __syncthreads();
    for (int s = 128; s > 0; s >>= 1) {
        if (tid < s) red[tid] = fmaxf(red[tid], red[tid + s]);
        __syncthreads();
    }
    m = red[0];
    __syncthreads();

    float sum = 0.0f;
    for (int j = tid; j < N; j += 256) {
        float e = expf(sv[j] - m);
        sv[j] = e;
        sum += e;
    }
    red[tid] = sum;
    __syncthreads();
    for (int s = 128; s > 0; s >>= 1) {
        if (tid < s) red[tid] += red[tid + s];
        __syncthreads();
    }
    float inv = 1.0f / red[0];
    for (int j = tid; j < N; j += 256) E[j] = sv[j] * inv;
}

// ---------------------------------------------------------------------------
// K3: out[b,c,j] = sum_i V[b,c,i] * A[b,i,j]; fused relu + y = gamma*out + x.
// grid (49, B), block (16,16). Output tile 128(c) x 64(j), K-chunk 32.
// ---------------------------------------------------------------------------
__global__ void k3_out(const float* __restrict__ x,
                       const float* __restrict__ gamma_p,
                       float* __restrict__ y_out,
                       float* __restrict__ o_out) {
    const int tjb = blockIdx.x, b = blockIdx.y;
    const float* V = x + (size_t)b * C * N;
    const float* A = g_E + (size_t)b * NN;

    __shared__ float As[128][33];  // [c][kk], padded
    __shared__ float Bs[32][64];   // [kk][j]

    const int tx = threadIdx.x, ty = threadIdx.y;
    const int tid = ty * 16 + tx;
    const int j0 = tjb * 64;

    float acc[8][4] = {};

    for (int k0 = 0; k0 < N; k0 += 32) {
        // As: 128x32 = 4096 elems -> 16 per thread, coalesced on kk
        #pragma unroll
        for (int r = 0; r < 16; r++) {
            int e = tid + r * 256;
            int cc = e >> 5, kk = e & 31;
            As[cc][kk] = V[(size_t)cc * N + k0 + kk];
        }
        // Bs: 32x64 = 2048 elems -> 8 per thread, coalesced on j
        #pragma unroll
        for (int r = 0; r < 8; r++) {
            int e = tid + r * 256;
            int kk = e >> 6, jj = e & 63;
            Bs[kk][jj] = A[(size_t)(k0 + kk) * N + j0 + jj];
        }
        __syncthreads();

        #pragma unroll
        for (int kk = 0; kk < 32; kk++) {
            float bb[4], a[8];
            #pragma unroll
            for (int s = 0; s < 4; s++) bb[s] = Bs[kk][tx * 4 + s];
            #pragma unroll
            for (int r = 0; r < 8; r++) a[r] = As[ty * 8 + r][kk];
            #pragma unroll
            for (int r = 0; r < 8; r++)
                #pragma unroll
                for (int s = 0; s < 4; s++)
                    acc[r][s] += a[r] * bb[s];
        }
        __syncthreads();
    }

    const float gamma = *gamma_p;
    #pragma unroll
    for (int r = 0; r < 8; r++) {
        int c = ty * 8 + r;
        #pragma unroll
        for (int s = 0; s < 4; s++) {
            int j = j0 + tx * 4 + s;
            size_t idx = (size_t)b * C * N + (size_t)c * N + j;
            float o = fmaxf(acc[r][s], 0.0f);
            o_out[idx] = o;
            y_out[idx] = gamma * o + x[idx];
        }
    }
}

// ---------------------------------------------------------------------------
// Launch: output layout = flattened tuple (y, out, x, gamma)
// ---------------------------------------------------------------------------
extern "C" void kernel_launch(void* const* d_in, const int* in_sizes, int n_in,
                              void* d_out, int out_size) {
    const float* x     = (const float*)d_in[0];
    const float* gamma = (const float*)d_in[1];
    float* out = (float*)d_out;

    float* y_sec = out;            // y
    float* o_sec = out + XE;       // out (post-relu)
    float* x_sec = out + 2 * XE;   // x passthrough
    float* g_sec = out + 3 * XE;   // gamma passthrough

    k1_gram<<<dim3(N / 64, N / 64, B), dim3(16, 16)>>>(x);
    k2_softmax<<<dim3(N, B), 256>>>();
    k3_out<<<dim3(N / 64, B), dim3(16, 16)>>>(x, gamma, y_sec, o_sec);

    cudaMemcpyAsync(x_sec, x, XE * sizeof(float), cudaMemcpyDeviceToDevice);
    cudaMemcpyAsync(g_sec, gamma, sizeof(float), cudaMemcpyDeviceToDevice);
}